// round 1
// baseline (speedup 1.0000x reference)
#include <cuda_runtime.h>
#include <cuda_bf16.h>

typedef unsigned long long u64;

#define NPTS   65536
#define CCH    64
#define NSMP   16
#define CSW    8
#define EPSV   1e-5f
#define NBW    4   // points (warps) per block in fused kernel

// ---------------- f32x2 helpers ----------------
__device__ __forceinline__ u64 pk2(float a, float b) {
    u64 r; asm("mov.b64 %0, {%1, %2};" : "=l"(r) : "f"(a), "f"(b)); return r;
}
__device__ __forceinline__ void upk2(u64 v, float& a, float& b) {
    asm("mov.b64 {%0, %1}, %2;" : "=f"(a), "=f"(b) : "l"(v));
}
__device__ __forceinline__ u64 ffma2(u64 a, u64 b, u64 c) {
    u64 d; asm("fma.rn.f32x2 %0, %1, %2, %3;" : "=l"(d) : "l"(a), "l"(b), "l"(c)); return d;
}
__device__ __forceinline__ u64 fadd2(u64 a, u64 b) {
    u64 d; asm("add.rn.f32x2 %0, %1, %2;" : "=l"(d) : "l"(a), "l"(b)); return d;
}

// ---------------- scratch tables (L2-resident: 3 x 16MB) ----------------
__device__ float g_xq[NPTS * CCH];
__device__ float g_xk[NPTS * CCH];
__device__ float g_xv[NPTS * CCH];

// =====================================================================
// Kernel 1: xq/xk/xv = x @ W^T + b   ([65536,64] x [64,64], 3 matrices)
// grid (1024, 3), block 256. Per-thread 4x4 tile, f32x2 packed FMA.
// =====================================================================
__global__ __launch_bounds__(256) void gemm_qkv(
    const float* __restrict__ x,
    const float* __restrict__ Wq, const float* __restrict__ bq,
    const float* __restrict__ Wk, const float* __restrict__ bk,
    const float* __restrict__ Wv, const float* __restrict__ bv)
{
    __shared__ float sX[64][68];  // sX[k][r] = x[row0+r][k]
    __shared__ float sW[64][68];  // sW[k][j] = W[j][k]
    __shared__ float sB[64];

    const int tid = threadIdx.x;
    const int mat = blockIdx.y;
    const float* W = (mat == 0) ? Wq : (mat == 1) ? Wk : Wv;
    const float* B = (mat == 0) ? bq : (mat == 1) ? bk : bv;
    float* outp    = (mat == 0) ? g_xq : (mat == 1) ? g_xk : g_xv;
    const int row0 = blockIdx.x * 64;

    // transpose-load x tile and W into smem
    const int r  = tid & 63;
    const int kb = (tid >> 6) << 4;
    #pragma unroll
    for (int e = 0; e < 4; ++e) {
        float4 vx = *(const float4*)&x[(row0 + r) * 64 + kb + 4 * e];
        sX[kb + 4 * e + 0][r] = vx.x; sX[kb + 4 * e + 1][r] = vx.y;
        sX[kb + 4 * e + 2][r] = vx.z; sX[kb + 4 * e + 3][r] = vx.w;
        float4 vw = *(const float4*)&W[r * 64 + kb + 4 * e];
        sW[kb + 4 * e + 0][r] = vw.x; sW[kb + 4 * e + 1][r] = vw.y;
        sW[kb + 4 * e + 2][r] = vw.z; sW[kb + 4 * e + 3][r] = vw.w;
    }
    if (tid < 64) sB[tid] = B[tid];
    __syncthreads();

    const int tx = tid & 15;   // col group: cols 4*tx..4*tx+3
    const int ty = tid >> 4;   // row group: rows 4*ty..4*ty+3

    u64 acc[2][4];
    #pragma unroll
    for (int c = 0; c < 4; ++c) {
        float bb = sB[4 * tx + c];
        u64 bd = pk2(bb, bb);
        acc[0][c] = bd; acc[1][c] = bd;
    }

    #pragma unroll
    for (int k = 0; k < 64; ++k) {
        u64 a0 = *(const u64*)&sX[k][4 * ty];       // rows 4ty, 4ty+1
        u64 a1 = *(const u64*)&sX[k][4 * ty + 2];   // rows 4ty+2, 4ty+3
        float4 b4 = *(const float4*)&sW[k][4 * tx];
        u64 b0 = pk2(b4.x, b4.x), b1 = pk2(b4.y, b4.y);
        u64 b2 = pk2(b4.z, b4.z), b3 = pk2(b4.w, b4.w);
        acc[0][0] = ffma2(a0, b0, acc[0][0]);  acc[1][0] = ffma2(a1, b0, acc[1][0]);
        acc[0][1] = ffma2(a0, b1, acc[0][1]);  acc[1][1] = ffma2(a1, b1, acc[1][1]);
        acc[0][2] = ffma2(a0, b2, acc[0][2]);  acc[1][2] = ffma2(a1, b2, acc[1][2]);
        acc[0][3] = ffma2(a0, b3, acc[0][3]);  acc[1][3] = ffma2(a1, b3, acc[1][3]);
    }

    #pragma unroll
    for (int rp = 0; rp < 2; ++rp) {
        float lo0, hi0, lo1, hi1, lo2, hi2, lo3, hi3;
        upk2(acc[rp][0], lo0, hi0); upk2(acc[rp][1], lo1, hi1);
        upk2(acc[rp][2], lo2, hi2); upk2(acc[rp][3], lo3, hi3);
        const int row = row0 + 4 * ty + 2 * rp;
        *(float4*)&outp[(row + 0) * 64 + 4 * tx] = make_float4(lo0, lo1, lo2, lo3);
        *(float4*)&outp[(row + 1) * 64 + 4 * tx] = make_float4(hi0, hi1, hi2, hi3);
    }
}

// =====================================================================
// Kernel 2: fused point-transformer. One warp per point.
//   Phase 0: lanes<16 compute per-neighbor positional t (3 vals)
//   Phase A: lane <-> channel-pair; coalesced xk/xv gather, compute
//            w = relu(bn1(xk - xq + pe)) and vpe = xv + pe into smem
//   Phase B: lane <-> (k, 4-output-group); w @ Ww1^T (f32x2), bn2/relu,
//            Ww2, logits -> smem
//   softmax over neighbors (lanes 0..7), weighted sum -> out
// =====================================================================
__global__ __launch_bounds__(128) void fused_pt(
    const float* __restrict__ p,   const int*   __restrict__ idx,
    const float* __restrict__ Wp1, const float* __restrict__ bp1,
    const float* __restrict__ pg,  const float* __restrict__ pb,
    const float* __restrict__ pm,  const float* __restrict__ pv,
    const float* __restrict__ Wp2, const float* __restrict__ bp2,
    const float* __restrict__ wg1, const float* __restrict__ wb1,
    const float* __restrict__ wm1, const float* __restrict__ wv1,
    const float* __restrict__ Ww1, const float* __restrict__ bw1,
    const float* __restrict__ wg2, const float* __restrict__ wb2,
    const float* __restrict__ wm2, const float* __restrict__ wv2,
    const float* __restrict__ Ww2, const float* __restrict__ bw2,
    float* __restrict__ out)
{
    // block-wide weights
    __shared__ float2 sW1p[32][8];   // {Ww1[o][2cp], Ww1[o][2cp+1]}
    __shared__ float  sW2[8][8];
    __shared__ float  sbw1[8], sa2[8], sb2[8], sbw2[8];
    __shared__ float  sWp1[9], sbp1v[3], spa[3], spbv[3];
    // per-warp (per point)
    __shared__ float  ssw [NBW][16][66];   // w[k][c]
    __shared__ float  svpe[NBW][16][66];   // (xv+pe)[k][c]
    __shared__ float2 stdp[NBW][16][3];    // {t,t} duplicated pairs
    __shared__ int    sj  [NBW][16];
    __shared__ float  swl [NBW][16][8];    // logits -> softmax weights

    const int tid = threadIdx.x;

    for (int i = tid; i < 512; i += 128) {
        int cp = i >> 4, rr = i & 15, o = rr >> 1, e = rr & 1;
        ((float*)sW1p)[i] = Ww1[o * 64 + 2 * cp + e];
    }
    if (tid < 64) sW2[tid >> 3][tid & 7] = Ww2[tid];
    if (tid < 8) {
        sbw1[tid] = bw1[tid];
        float a = wg2[tid] * rsqrtf(wv2[tid] + EPSV);
        sa2[tid] = a; sb2[tid] = wb2[tid] - wm2[tid] * a;
        sbw2[tid] = bw2[tid];
    }
    if (tid < 9) sWp1[tid] = Wp1[tid];
    if (tid < 3) {
        sbp1v[tid] = bp1[tid];
        float a = pg[tid] * rsqrtf(pv[tid] + EPSV);
        spa[tid] = a; spbv[tid] = pb[tid] - pm[tid] * a;
    }
    __syncthreads();

    const int w    = tid >> 5;
    const int lane = tid & 31;
    const int n    = blockIdx.x * NBW + w;
    const int k    = lane & 15;
    const int og   = lane >> 4;
    const int c0   = 2 * lane;   // channel pair owned in phase A

    // per-lane constants (channel pair c0, c0+1)
    const u64 xq2   = *(const u64*)&g_xq[n * 64 + c0];
    const u64 wpj0  = pk2(Wp2[c0 * 3 + 0], Wp2[c0 * 3 + 3]);
    const u64 wpj1  = pk2(Wp2[c0 * 3 + 1], Wp2[c0 * 3 + 4]);
    const u64 wpj2  = pk2(Wp2[c0 * 3 + 2], Wp2[c0 * 3 + 5]);
    const u64 bp2d  = pk2(bp2[c0], bp2[c0 + 1]);
    float a1_0 = wg1[c0] * rsqrtf(wv1[c0] + EPSV);
    float b1_0 = wb1[c0] - wm1[c0] * a1_0;
    float a1_1 = wg1[c0 + 1] * rsqrtf(wv1[c0 + 1] + EPSV);
    float b1_1 = wb1[c0 + 1] - wm1[c0 + 1] * a1_1;
    const u64 negone = pk2(-1.0f, -1.0f);

    // ---- Phase 0: neighbor t values ----
    if (lane < 16) {
        int j = idx[n * 16 + lane];
        sj[w][lane] = j;
        float pnx = p[n * 3 + 0], pny = p[n * 3 + 1], pnz = p[n * 3 + 2];
        float prx = p[j * 3 + 0] - pnx;
        float pry = p[j * 3 + 1] - pny;
        float prz = p[j * 3 + 2] - pnz;
        float u0 = prx * sWp1[0] + pry * sWp1[1] + prz * sWp1[2] + sbp1v[0];
        float u1 = prx * sWp1[3] + pry * sWp1[4] + prz * sWp1[5] + sbp1v[1];
        float u2 = prx * sWp1[6] + pry * sWp1[7] + prz * sWp1[8] + sbp1v[2];
        float t0 = fmaxf(0.f, fmaf(u0, spa[0], spbv[0]));
        float t1 = fmaxf(0.f, fmaf(u1, spa[1], spbv[1]));
        float t2 = fmaxf(0.f, fmaf(u2, spa[2], spbv[2]));
        stdp[w][lane][0] = make_float2(t0, t0);
        stdp[w][lane][1] = make_float2(t1, t1);
        stdp[w][lane][2] = make_float2(t2, t2);
    }
    __syncwarp();

    // ---- Phase A: gather + relation + pos-enc ----
    #pragma unroll
    for (int kk = 0; kk < 16; ++kk) {
        int j    = sj[w][kk];
        u64 t0d  = *(const u64*)&stdp[w][kk][0];
        u64 t1d  = *(const u64*)&stdp[w][kk][1];
        u64 t2d  = *(const u64*)&stdp[w][kk][2];
        u64 xk2v = *(const u64*)&g_xk[j * 64 + c0];   // coalesced: 2 lines/warp
        u64 xv2v = *(const u64*)&g_xv[j * 64 + c0];
        u64 pe2  = ffma2(wpj0, t0d, ffma2(wpj1, t1d, ffma2(wpj2, t2d, bp2d)));
        u64 r2   = fadd2(ffma2(xq2, negone, xk2v), pe2);  // xk - xq + pe
        float r_0, r_1; upk2(r2, r_0, r_1);
        float w_0 = fmaxf(0.f, fmaf(r_0, a1_0, b1_0));
        float w_1 = fmaxf(0.f, fmaf(r_1, a1_1, b1_1));
        *(u64*)&ssw [w][kk][c0] = pk2(w_0, w_1);
        *(u64*)&svpe[w][kk][c0] = fadd2(xv2v, pe2);
    }
    __syncwarp();

    // ---- Phase B: w @ Ww1^T -> bn2/relu -> Ww2 -> logits ----
    u64 pacc[4] = {0ull, 0ull, 0ull, 0ull};
    #pragma unroll
    for (int cp = 0; cp < 32; ++cp) {
        u64 w2 = *(const u64*)&ssw[w][k][2 * cp];
        const ulonglong2* wr = (const ulonglong2*)&sW1p[cp][og * 4];
        ulonglong2 w01 = wr[0], w23 = wr[1];
        pacc[0] = ffma2(w2, w01.x, pacc[0]);
        pacc[1] = ffma2(w2, w01.y, pacc[1]);
        pacc[2] = ffma2(w2, w23.x, pacc[2]);
        pacc[3] = ffma2(w2, w23.y, pacc[3]);
    }
    float hmine[4];
    #pragma unroll
    for (int m = 0; m < 4; ++m) {
        float lo, hi; upk2(pacc[m], lo, hi);
        int o = og * 4 + m;
        float tot = lo + hi + sbw1[o];
        hmine[m] = fmaxf(0.f, fmaf(tot, sa2[o], sb2[o]));
    }
    float hoth[4];
    #pragma unroll
    for (int m = 0; m < 4; ++m)
        hoth[m] = __shfl_xor_sync(0xffffffffu, hmine[m], 16);

    const int omine = og * 4, ooth = omine ^ 4;
    if (og == 0) {
        #pragma unroll
        for (int o2 = 0; o2 < 8; ++o2) {
            float lg = sbw2[o2];
            #pragma unroll
            for (int m = 0; m < 4; ++m) {
                lg = fmaf(hmine[m], sW2[o2][omine + m], lg);
                lg = fmaf(hoth[m],  sW2[o2][ooth  + m], lg);
            }
            swl[w][k][o2] = lg;
        }
    }
    __syncwarp();

    // ---- softmax over the 16 neighbors (per CS channel) ----
    if (lane < 8) {
        float vals[16];
        float mx = -1e30f;
        #pragma unroll
        for (int kk = 0; kk < 16; ++kk) { vals[kk] = swl[w][kk][lane]; mx = fmaxf(mx, vals[kk]); }
        float s = 0.f;
        #pragma unroll
        for (int kk = 0; kk < 16; ++kk) { vals[kk] = __expf(vals[kk] - mx); s += vals[kk]; }
        float inv = 1.f / s;
        #pragma unroll
        for (int kk = 0; kk < 16; ++kk) swl[w][kk][lane] = vals[kk] * inv;
    }
    __syncwarp();

    // ---- weighted sum over neighbors ----
    float acc0 = 0.f, acc1 = 0.f;
    const int cs = lane & 7;
    #pragma unroll
    for (int kk = 0; kk < 16; ++kk) {
        float g = swl[w][kk][cs];
        acc0 = fmaf(svpe[w][kk][lane],      g, acc0);
        acc1 = fmaf(svpe[w][kk][lane + 32], g, acc1);
    }
    out[n * 64 + lane]      = acc0;
    out[n * 64 + lane + 32] = acc1;
}

// =====================================================================
extern "C" void kernel_launch(void* const* d_in, const int* in_sizes, int n_in,
                              void* d_out, int out_size)
{
    const float* p   = (const float*)d_in[0];
    const float* x   = (const float*)d_in[1];
    const int*   idx = (const int*)  d_in[2];
    const float* Wq  = (const float*)d_in[3];
    const float* bq  = (const float*)d_in[4];
    const float* Wk  = (const float*)d_in[5];
    const float* bk  = (const float*)d_in[6];
    const float* Wv  = (const float*)d_in[7];
    const float* bv  = (const float*)d_in[8];
    const float* Wp1 = (const float*)d_in[9];
    const float* bp1 = (const float*)d_in[10];
    const float* pg  = (const float*)d_in[11];
    const float* pb  = (const float*)d_in[12];
    const float* pm  = (const float*)d_in[13];
    const float* pv  = (const float*)d_in[14];
    const float* Wp2 = (const float*)d_in[15];
    const float* bp2 = (const float*)d_in[16];
    const float* wg1 = (const float*)d_in[17];
    const float* wb1 = (const float*)d_in[18];
    const float* wm1 = (const float*)d_in[19];
    const float* wv1 = (const float*)d_in[20];
    const float* Ww1 = (const float*)d_in[21];
    const float* bw1 = (const float*)d_in[22];
    const float* wg2 = (const float*)d_in[23];
    const float* wb2 = (const float*)d_in[24];
    const float* wm2 = (const float*)d_in[25];
    const float* wv2 = (const float*)d_in[26];
    const float* Ww2 = (const float*)d_in[27];
    const float* bw2 = (const float*)d_in[28];
    float* out = (float*)d_out;

    gemm_qkv<<<dim3(NPTS / 64, 3, 1), 256>>>(x, Wq, bq, Wk, bk, Wv, bv);
    fused_pt<<<NPTS / NBW, 128>>>(p, idx, Wp1, bp1, pg, pb, pm, pv, Wp2, bp2,
                                  wg1, wb1, wm1, wv1, Ww1, bw1,
                                  wg2, wb2, wm2, wv2, Ww2, bw2, out);
}

// round 2
// speedup vs baseline: 1.1921x; 1.1921x over previous
#include <cuda_runtime.h>
#include <cuda_bf16.h>

typedef unsigned long long u64;

#define NPTS   65536
#define CCH    64
#define NSMP   16
#define CSW    8
#define EPSV   1e-5f
#define NBW    4   // points (warps) per block in fused kernel

// ---------------- f32x2 helpers ----------------
__device__ __forceinline__ u64 pk2(float a, float b) {
    u64 r; asm("mov.b64 %0, {%1, %2};" : "=l"(r) : "f"(a), "f"(b)); return r;
}
__device__ __forceinline__ void upk2(u64 v, float& a, float& b) {
    asm("mov.b64 {%0, %1}, %2;" : "=f"(a), "=f"(b) : "l"(v));
}
__device__ __forceinline__ u64 ffma2(u64 a, u64 b, u64 c) {
    u64 d; asm("fma.rn.f32x2 %0, %1, %2, %3;" : "=l"(d) : "l"(a), "l"(b), "l"(c)); return d;
}
__device__ __forceinline__ u64 fadd2(u64 a, u64 b) {
    u64 d; asm("add.rn.f32x2 %0, %1, %2;" : "=l"(d) : "l"(a), "l"(b)); return d;
}

// ---------------- scratch tables (L2-resident: 3 x 16MB) ----------------
__device__ float g_xq[NPTS * CCH];
__device__ float g_xk[NPTS * CCH];
__device__ float g_xv[NPTS * CCH];

// =====================================================================
// Kernel 1: xq/xk/xv = x @ W^T + b   ([65536,64] x [64,64], 3 matrices)
// =====================================================================
__global__ __launch_bounds__(256) void gemm_qkv(
    const float* __restrict__ x,
    const float* __restrict__ Wq, const float* __restrict__ bq,
    const float* __restrict__ Wk, const float* __restrict__ bk,
    const float* __restrict__ Wv, const float* __restrict__ bv)
{
    __shared__ float sX[64][68];  // sX[k][r] = x[row0+r][k]
    __shared__ float sW[64][68];  // sW[k][j] = W[j][k]
    __shared__ float sB[64];

    const int tid = threadIdx.x;
    const int mat = blockIdx.y;
    const float* W = (mat == 0) ? Wq : (mat == 1) ? Wk : Wv;
    const float* B = (mat == 0) ? bq : (mat == 1) ? bk : bv;
    float* outp    = (mat == 0) ? g_xq : (mat == 1) ? g_xk : g_xv;
    const int row0 = blockIdx.x * 64;

    const int r  = tid & 63;
    const int kb = (tid >> 6) << 4;
    #pragma unroll
    for (int e = 0; e < 4; ++e) {
        float4 vx = *(const float4*)&x[(row0 + r) * 64 + kb + 4 * e];
        sX[kb + 4 * e + 0][r] = vx.x; sX[kb + 4 * e + 1][r] = vx.y;
        sX[kb + 4 * e + 2][r] = vx.z; sX[kb + 4 * e + 3][r] = vx.w;
        float4 vw = *(const float4*)&W[r * 64 + kb + 4 * e];
        sW[kb + 4 * e + 0][r] = vw.x; sW[kb + 4 * e + 1][r] = vw.y;
        sW[kb + 4 * e + 2][r] = vw.z; sW[kb + 4 * e + 3][r] = vw.w;
    }
    if (tid < 64) sB[tid] = B[tid];
    __syncthreads();

    const int tx = tid & 15;
    const int ty = tid >> 4;

    u64 acc[2][4];
    #pragma unroll
    for (int c = 0; c < 4; ++c) {
        float bb = sB[4 * tx + c];
        u64 bd = pk2(bb, bb);
        acc[0][c] = bd; acc[1][c] = bd;
    }

    #pragma unroll
    for (int k = 0; k < 64; ++k) {
        u64 a0 = *(const u64*)&sX[k][4 * ty];
        u64 a1 = *(const u64*)&sX[k][4 * ty + 2];
        float4 b4 = *(const float4*)&sW[k][4 * tx];
        u64 b0 = pk2(b4.x, b4.x), b1 = pk2(b4.y, b4.y);
        u64 b2 = pk2(b4.z, b4.z), b3 = pk2(b4.w, b4.w);
        acc[0][0] = ffma2(a0, b0, acc[0][0]);  acc[1][0] = ffma2(a1, b0, acc[1][0]);
        acc[0][1] = ffma2(a0, b1, acc[0][1]);  acc[1][1] = ffma2(a1, b1, acc[1][1]);
        acc[0][2] = ffma2(a0, b2, acc[0][2]);  acc[1][2] = ffma2(a1, b2, acc[1][2]);
        acc[0][3] = ffma2(a0, b3, acc[0][3]);  acc[1][3] = ffma2(a1, b3, acc[1][3]);
    }

    #pragma unroll
    for (int rp = 0; rp < 2; ++rp) {
        float lo0, hi0, lo1, hi1, lo2, hi2, lo3, hi3;
        upk2(acc[rp][0], lo0, hi0); upk2(acc[rp][1], lo1, hi1);
        upk2(acc[rp][2], lo2, hi2); upk2(acc[rp][3], lo3, hi3);
        const int row = row0 + 4 * ty + 2 * rp;
        *(float4*)&outp[(row + 0) * 64 + 4 * tx] = make_float4(lo0, lo1, lo2, lo3);
        *(float4*)&outp[(row + 1) * 64 + 4 * tx] = make_float4(hi0, hi1, hi2, hi3);
    }
}

// =====================================================================
// Kernel 2: fused point-transformer. One warp per point.
//   Phase 0: lanes<16 compute per-neighbor positional t (3 vals)
//   Phase A: lane <-> channel-pair; coalesced xk gather ->
//            w = relu(bn1(xk - xq + pe)) into smem
//   Phase B: lane <-> (k, og); w @ Ww1^T (f32x2), bn2/relu, Ww2 -> logits
//   softmax over neighbors; Phase C: re-gather xv, recompute pe,
//   weighted sum -> out.  64-reg cap, 8 blocks/SM target.
// =====================================================================
__global__ void __launch_bounds__(128, 8) fused_pt(
    const float* __restrict__ p,   const int*   __restrict__ idx,
    const float* __restrict__ Wp1, const float* __restrict__ bp1,
    const float* __restrict__ pg,  const float* __restrict__ pb,
    const float* __restrict__ pm,  const float* __restrict__ pv,
    const float* __restrict__ Wp2, const float* __restrict__ bp2,
    const float* __restrict__ wg1, const float* __restrict__ wb1,
    const float* __restrict__ wm1, const float* __restrict__ wv1,
    const float* __restrict__ Ww1, const float* __restrict__ bw1,
    const float* __restrict__ wg2, const float* __restrict__ wb2,
    const float* __restrict__ wm2, const float* __restrict__ wv2,
    const float* __restrict__ Ww2, const float* __restrict__ bw2,
    float* __restrict__ out)
{
    // block-wide weights
    __shared__ float2 sW1p[32][8];   // {Ww1[o][2cp], Ww1[o][2cp+1]}
    __shared__ float  sW2[8][8];
    __shared__ float  sbw1[8], sa2[8], sb2[8], sbw2[8];
    __shared__ float  sWp1[9], sbp1v[3], spa[3], spbv[3];
    // per-warp (per point)
    __shared__ float  ssw [NBW][16][66];   // w[k][c]
    __shared__ float  stv [NBW][16][3];    // t values per neighbor
    __shared__ int    sj  [NBW][16];
    __shared__ float  swl [NBW][16][8];    // logits -> softmax weights

    const int tid = threadIdx.x;

    for (int i = tid; i < 512; i += 128) {
        int cp = i >> 4, rr = i & 15, o = rr >> 1, e = rr & 1;
        ((float*)sW1p)[i] = Ww1[o * 64 + 2 * cp + e];
    }
    if (tid < 64) sW2[tid >> 3][tid & 7] = Ww2[tid];
    if (tid < 8) {
        sbw1[tid] = bw1[tid];
        float a = wg2[tid] * rsqrtf(wv2[tid] + EPSV);
        sa2[tid] = a; sb2[tid] = wb2[tid] - wm2[tid] * a;
        sbw2[tid] = bw2[tid];
    }
    if (tid < 9) sWp1[tid] = Wp1[tid];
    if (tid < 3) {
        sbp1v[tid] = bp1[tid];
        float a = pg[tid] * rsqrtf(pv[tid] + EPSV);
        spa[tid] = a; spbv[tid] = pb[tid] - pm[tid] * a;
    }
    __syncthreads();

    const int w    = tid >> 5;
    const int lane = tid & 31;
    const int n    = blockIdx.x * NBW + w;
    const int c0   = 2 * lane;   // channel pair owned in phases A & C

    // ---- Phase 0: neighbor t values ----
    if (lane < 16) {
        int j = idx[n * 16 + lane];
        sj[w][lane] = j;
        float pnx = p[n * 3 + 0], pny = p[n * 3 + 1], pnz = p[n * 3 + 2];
        float prx = p[j * 3 + 0] - pnx;
        float pry = p[j * 3 + 1] - pny;
        float prz = p[j * 3 + 2] - pnz;
        float u0 = prx * sWp1[0] + pry * sWp1[1] + prz * sWp1[2] + sbp1v[0];
        float u1 = prx * sWp1[3] + pry * sWp1[4] + prz * sWp1[5] + sbp1v[1];
        float u2 = prx * sWp1[6] + pry * sWp1[7] + prz * sWp1[8] + sbp1v[2];
        stv[w][lane][0] = fmaxf(0.f, fmaf(u0, spa[0], spbv[0]));
        stv[w][lane][1] = fmaxf(0.f, fmaf(u1, spa[1], spbv[1]));
        stv[w][lane][2] = fmaxf(0.f, fmaf(u2, spa[2], spbv[2]));
    }
    __syncwarp();

    // ---- Phase A: gather xk + relation + pos-enc -> ssw ----
    {
        const u64 xq2  = *(const u64*)&g_xq[n * 64 + c0];
        const u64 wpj0 = pk2(Wp2[c0 * 3 + 0], Wp2[c0 * 3 + 3]);
        const u64 wpj1 = pk2(Wp2[c0 * 3 + 1], Wp2[c0 * 3 + 4]);
        const u64 wpj2 = pk2(Wp2[c0 * 3 + 2], Wp2[c0 * 3 + 5]);
        const u64 bp2d = pk2(bp2[c0], bp2[c0 + 1]);
        float a1_0 = wg1[c0] * rsqrtf(wv1[c0] + EPSV);
        float b1_0 = wb1[c0] - wm1[c0] * a1_0;
        float a1_1 = wg1[c0 + 1] * rsqrtf(wv1[c0 + 1] + EPSV);
        float b1_1 = wb1[c0 + 1] - wm1[c0 + 1] * a1_1;
        const u64 negone = pk2(-1.0f, -1.0f);

        #pragma unroll
        for (int kk = 0; kk < 16; ++kk) {
            int j   = sj[w][kk];
            float t0 = stv[w][kk][0], t1 = stv[w][kk][1], t2 = stv[w][kk][2];
            u64 xk2v = *(const u64*)&g_xk[j * 64 + c0];   // coalesced
            u64 pe2  = ffma2(wpj0, pk2(t0, t0),
                       ffma2(wpj1, pk2(t1, t1),
                       ffma2(wpj2, pk2(t2, t2), bp2d)));
            u64 r2   = fadd2(ffma2(xq2, negone, xk2v), pe2);  // xk - xq + pe
            float r_0, r_1; upk2(r2, r_0, r_1);
            float w_0 = fmaxf(0.f, fmaf(r_0, a1_0, b1_0));
            float w_1 = fmaxf(0.f, fmaf(r_1, a1_1, b1_1));
            *(u64*)&ssw[w][kk][c0] = pk2(w_0, w_1);
        }
    }
    __syncwarp();

    // ---- Phase B: w @ Ww1^T -> bn2/relu -> Ww2 -> logits ----
    {
        const int k  = lane & 15;
        const int og = lane >> 4;
        u64 pacc[4] = {0ull, 0ull, 0ull, 0ull};
        #pragma unroll
        for (int cp = 0; cp < 32; ++cp) {
            u64 w2 = *(const u64*)&ssw[w][k][2 * cp];
            const ulonglong2* wr = (const ulonglong2*)&sW1p[cp][og * 4];
            ulonglong2 w01 = wr[0], w23 = wr[1];
            pacc[0] = ffma2(w2, w01.x, pacc[0]);
            pacc[1] = ffma2(w2, w01.y, pacc[1]);
            pacc[2] = ffma2(w2, w23.x, pacc[2]);
            pacc[3] = ffma2(w2, w23.y, pacc[3]);
        }
        float hmine[4];
        #pragma unroll
        for (int m = 0; m < 4; ++m) {
            float lo, hi; upk2(pacc[m], lo, hi);
            int o = og * 4 + m;
            float tot = lo + hi + sbw1[o];
            hmine[m] = fmaxf(0.f, fmaf(tot, sa2[o], sb2[o]));
        }
        float hoth[4];
        #pragma unroll
        for (int m = 0; m < 4; ++m)
            hoth[m] = __shfl_xor_sync(0xffffffffu, hmine[m], 16);

        const int omine = og * 4, ooth = omine ^ 4;
        if (og == 0) {
            #pragma unroll
            for (int o2 = 0; o2 < 8; ++o2) {
                float lg = sbw2[o2];
                #pragma unroll
                for (int m = 0; m < 4; ++m) {
                    lg = fmaf(hmine[m], sW2[o2][omine + m], lg);
                    lg = fmaf(hoth[m],  sW2[o2][ooth  + m], lg);
                }
                swl[w][k][o2] = lg;
            }
        }
    }
    __syncwarp();

    // ---- softmax over the 16 neighbors (register-light, lanes 0..7) ----
    if (lane < 8) {
        float mx = -1e30f;
        #pragma unroll
        for (int kk = 0; kk < 16; ++kk) mx = fmaxf(mx, swl[w][kk][lane]);
        float s = 0.f;
        #pragma unroll
        for (int kk = 0; kk < 16; ++kk) s += __expf(swl[w][kk][lane] - mx);
        float inv = 1.f / s;
        #pragma unroll
        for (int kk = 0; kk < 16; ++kk)
            swl[w][kk][lane] = __expf(swl[w][kk][lane] - mx) * inv;
    }
    __syncwarp();

    // ---- Phase C: re-gather xv, recompute pe, weighted sum ----
    {
        const u64 wpj0 = pk2(Wp2[c0 * 3 + 0], Wp2[c0 * 3 + 3]);
        const u64 wpj1 = pk2(Wp2[c0 * 3 + 1], Wp2[c0 * 3 + 4]);
        const u64 wpj2 = pk2(Wp2[c0 * 3 + 2], Wp2[c0 * 3 + 5]);
        const u64 bp2d = pk2(bp2[c0], bp2[c0 + 1]);
        const int cs   = c0 & 7;   // even, so pair (cs, cs+1)

        u64 acc = 0ull;
        #pragma unroll
        for (int kk = 0; kk < 16; ++kk) {
            int j   = sj[w][kk];
            float t0 = stv[w][kk][0], t1 = stv[w][kk][1], t2 = stv[w][kk][2];
            u64 xv2v = *(const u64*)&g_xv[j * 64 + c0];   // coalesced
            u64 pe2  = ffma2(wpj0, pk2(t0, t0),
                       ffma2(wpj1, pk2(t1, t1),
                       ffma2(wpj2, pk2(t2, t2), bp2d)));
            u64 g2   = *(const u64*)&swl[w][kk][cs];      // weight pair
            acc = ffma2(fadd2(xv2v, pe2), g2, acc);
        }
        float o0, o1; upk2(acc, o0, o1);
        *(float2*)&out[n * 64 + c0] = make_float2(o0, o1);
    }
}

// =====================================================================
extern "C" void kernel_launch(void* const* d_in, const int* in_sizes, int n_in,
                              void* d_out, int out_size)
{
    const float* p   = (const float*)d_in[0];
    const float* x   = (const float*)d_in[1];
    const int*   idx = (const int*)  d_in[2];
    const float* Wq  = (const float*)d_in[3];
    const float* bq  = (const float*)d_in[4];
    const float* Wk  = (const float*)d_in[5];
    const float* bk  = (const float*)d_in[6];
    const float* Wv  = (const float*)d_in[7];
    const float* bv  = (const float*)d_in[8];
    const float* Wp1 = (const float*)d_in[9];
    const float* bp1 = (const float*)d_in[10];
    const float* pg  = (const float*)d_in[11];
    const float* pb  = (const float*)d_in[12];
    const float* pm  = (const float*)d_in[13];
    const float* pv  = (const float*)d_in[14];
    const float* Wp2 = (const float*)d_in[15];
    const float* bp2 = (const float*)d_in[16];
    const float* wg1 = (const float*)d_in[17];
    const float* wb1 = (const float*)d_in[18];
    const float* wm1 = (const float*)d_in[19];
    const float* wv1 = (const float*)d_in[20];
    const float* Ww1 = (const float*)d_in[21];
    const float* bw1 = (const float*)d_in[22];
    const float* wg2 = (const float*)d_in[23];
    const float* wb2 = (const float*)d_in[24];
    const float* wm2 = (const float*)d_in[25];
    const float* wv2 = (const float*)d_in[26];
    const float* Ww2 = (const float*)d_in[27];
    const float* bw2 = (const float*)d_in[28];
    float* out = (float*)d_out;

    gemm_qkv<<<dim3(NPTS / 64, 3, 1), 256>>>(x, Wq, bq, Wk, bk, Wv, bv);
    fused_pt<<<NPTS / NBW, 128>>>(p, idx, Wp1, bp1, pg, pb, pm, pv, Wp2, bp2,
                                  wg1, wb1, wm1, wv1, Ww1, bw1,
                                  wg2, wb2, wm2, wv2, Ww2, bw2, out);
}